// round 15
// baseline (speedup 1.0000x reference)
#include <cuda_runtime.h>
#include <cuda_fp16.h>
#include <cstdint>

// Problem constants
#define BB 4
#define SS 2048
#define DD 768
#define HH 12
#define DH 64
#define MM (BB * SS)   // 8192 rows

// Scratch: fp16 copies of inputs + projections
__device__ __half g_xh[MM * DD];
__device__ __half g_wh[3 * DD * DD];
__device__ __half g_q[MM * DD];
__device__ __half g_k[MM * DD];
__device__ __half g_v[MM * DD];

__device__ __forceinline__ void mma_f16(float* c,
    uint32_t a0, uint32_t a1, uint32_t a2, uint32_t a3,
    uint32_t b0, uint32_t b1)
{
    asm volatile(
        "mma.sync.aligned.m16n8k16.row.col.f32.f16.f16.f32 "
        "{%0,%1,%2,%3},{%4,%5,%6,%7},{%8,%9},{%0,%1,%2,%3};"
        : "+f"(c[0]), "+f"(c[1]), "+f"(c[2]), "+f"(c[3])
        : "r"(a0), "r"(a1), "r"(a2), "r"(a3), "r"(b0), "r"(b1));
}

__device__ __forceinline__ void ldsm_x4(uint32_t& r0, uint32_t& r1,
    uint32_t& r2, uint32_t& r3, uint32_t addr)
{
    asm volatile("ldmatrix.sync.aligned.m8n8.x4.shared.b16 {%0,%1,%2,%3}, [%4];"
        : "=r"(r0), "=r"(r1), "=r"(r2), "=r"(r3) : "r"(addr));
}

__device__ __forceinline__ void ldsm_x4_t(uint32_t& r0, uint32_t& r1,
    uint32_t& r2, uint32_t& r3, uint32_t addr)
{
    asm volatile("ldmatrix.sync.aligned.m8n8.x4.trans.shared.b16 {%0,%1,%2,%3}, [%4];"
        : "=r"(r0), "=r"(r1), "=r"(r2), "=r"(r3) : "r"(addr));
}

__device__ __forceinline__ uint32_t pack_h2(float a, float b) {
    __half2 h = __floats2half2_rn(a, b);
    return *(uint32_t*)&h;
}

__device__ __forceinline__ uint32_t h2exp2(uint32_t x) {
    uint32_t r;
    asm("ex2.approx.f16x2 %0, %1;" : "=r"(r) : "r"(x));
    return r;
}

#define CP16(dst, src) \
    asm volatile("cp.async.cg.shared.global [%0], [%1], 16;" :: "r"(dst), "l"(src))
#define CP_COMMIT() asm volatile("cp.async.commit_group;")
#define CP_WAIT1()  asm volatile("cp.async.wait_group 1;")
#define CP_WAIT0()  asm volatile("cp.async.wait_group 0;")

#define SCL 0.18033688f   // 0.125 * log2(e), folded into Q projection
#define MASKV (-64.0f)    // exp2(-64) == 0 in fp16

// ---------------------------------------------------------------------------
// fp32 -> fp16 conversion: packed 1-D grid, 8 elems/thread (R13 shape).
// ---------------------------------------------------------------------------
#define XB (MM * DD / 8 / 256)     // 3072 blocks
#define WB (DD * DD / 8 / 256)     // 288 blocks

__global__ __launch_bounds__(256) void cvt_pack(
    const float* __restrict__ X,
    const float* __restrict__ wq, const float* __restrict__ wk,
    const float* __restrict__ wv,
    __half* __restrict__ xh, __half* __restrict__ wh)
{
    int bid = blockIdx.x;
    const float* src;
    __half* dst;
    if (bid < XB) {
        src = X; dst = xh;
    } else {
        bid -= XB;
        const int z = bid / WB;
        bid -= z * WB;
        src = (z == 0) ? wq : (z == 1) ? wk : wv;
        dst = wh + (long)z * DD * DD;
    }
    const long i = ((long)bid * 256 + threadIdx.x) * 8;
    float4 a = *(const float4*)&src[i];
    float4 b = *(const float4*)&src[i + 4];
    uint4 o;
    o.x = pack_h2(a.x, a.y);
    o.y = pack_h2(a.z, a.w);
    o.z = pack_h2(b.x, b.y);
    o.w = pack_h2(b.z, b.w);
    *(uint4*)&dst[i] = o;
}

// ---------------------------------------------------------------------------
// fp16 projection GEMM: BK=64, 3-stage cp.async, flat grid (frozen).
// z==0 (Q) output is pre-scaled by 0.125*log2(e).
// ---------------------------------------------------------------------------
#define HAS 72
#define HBS 136
#define ATB (128 * HAS * 2)   // 18432 B
#define BTB (64 * HBS * 2)    // 17408 B
#define NSTG 3

__global__ __launch_bounds__(256, 2) void gemm_h(
    const __half* __restrict__ Xh, const __half* __restrict__ Wh,
    const float* __restrict__ bq, const float* __restrict__ bk,
    const float* __restrict__ bv,
    __half* __restrict__ oq, __half* __restrict__ okk, __half* __restrict__ ov)
{
    const int z  = blockIdx.x / (DD / 128);
    const int nt = blockIdx.x % (DD / 128);
    const __half* W   = Wh + (long)z * DD * DD;
    const float* bias = (z == 0) ? bq : (z == 1) ? bk : bv;
    __half* out       = (z == 0) ? oq : (z == 1) ? okk : ov;
    const float esc   = (z == 0) ? SCL : 1.0f;

    extern __shared__ __align__(16) char smc[];
    const uint32_t sb  = (uint32_t)__cvta_generic_to_shared(smc);
    const uint32_t Asa = sb;
    const uint32_t Bsa = sb + NSTG * ATB;

    const int tid  = threadIdx.x;
    const int lane = tid & 31;
    const int w    = tid >> 5;
    const int g    = lane >> 2;
    const int qd   = lane & 3;
    const int wm   = w >> 2;
    const int wn   = w & 3;
    const int m0   = blockIdx.y * 128;
    const int n0   = nt * 128;

    float acc[4][4][4];
#pragma unroll
    for (int mf = 0; mf < 4; mf++)
#pragma unroll
        for (int j = 0; j < 4; j++)
#pragma unroll
            for (int q = 0; q < 4; q++) acc[mf][j][q] = 0.f;

#define LOADT(t, bsel)                                                        \
    {                                                                         \
        const int k0 = (t) * 64;                                              \
        _Pragma("unroll")                                                     \
        for (int i = 0; i < 4; i++) {                                         \
            int ch = i * 256 + tid;                                           \
            int r = ch >> 3, c = (ch & 7) * 8;                                \
            CP16(Asa + (bsel) * ATB + (r * HAS + c) * 2,                      \
                 &Xh[(long)(m0 + r) * DD + k0 + c]);                          \
        }                                                                     \
        _Pragma("unroll")                                                     \
        for (int i = 0; i < 4; i++) {                                         \
            int ch = i * 256 + tid;                                           \
            int r = ch >> 4, c = (ch & 15) * 8;                               \
            CP16(Bsa + (bsel) * BTB + (r * HBS + c) * 2,                      \
                 &W[(long)(k0 + r) * DD + n0 + c]);                           \
        }                                                                     \
        CP_COMMIT();                                                          \
    }

    LOADT(0, 0);
    LOADT(1, 1);

    const uint32_t aB = ((lane & 15) * HAS + ((lane & 16) >> 1)) * 2;
    const uint32_t bB = (((lane & 7) + (lane & 8)) * HBS + ((lane & 16) >> 1)) * 2;

    const int T = DD / 64;   // 12
#pragma unroll 1
    for (int t = 0; t < T; t++) {
        CP_WAIT1();
        __syncthreads();
        const int buf = t % NSTG;
        const uint32_t Ab = Asa + buf * ATB + aB + (wm * 64 * HAS) * 2;
        const uint32_t Bb = Bsa + buf * BTB + bB + (wn * 32) * 2;

        if (t + 2 < T) {
            LOADT(t + 2, (t + 2) % NSTG);
        } else {
            CP_COMMIT();
        }

#pragma unroll
        for (int ks = 0; ks < 4; ks++) {
            uint32_t a[4][4];
#pragma unroll
            for (int mf = 0; mf < 4; mf++)
                ldsm_x4(a[mf][0], a[mf][1], a[mf][2], a[mf][3],
                        Ab + (mf * 16 * HAS + ks * 16) * 2);
#pragma unroll
            for (int nf = 0; nf < 2; nf++) {
                uint32_t b0, b1, b2, b3;
                ldsm_x4_t(b0, b1, b2, b3, Bb + (ks * 16 * HBS + nf * 16) * 2);
#pragma unroll
                for (int mf = 0; mf < 4; mf++) {
                    mma_f16(acc[mf][2 * nf],     a[mf][0], a[mf][1], a[mf][2], a[mf][3], b0, b1);
                    mma_f16(acc[mf][2 * nf + 1], a[mf][0], a[mf][1], a[mf][2], a[mf][3], b2, b3);
                }
            }
        }
    }

#pragma unroll
    for (int mf = 0; mf < 4; mf++) {
        const int row0 = m0 + wm * 64 + mf * 16 + g;
#pragma unroll
        for (int j = 0; j < 4; j++) {
            const int col = n0 + wn * 32 + j * 8 + 2 * qd;
            const float bx = __ldg(&bias[col]);
            const float by = __ldg(&bias[col + 1]);
            __half2 h0 = __floats2half2_rn((acc[mf][j][0] + bx) * esc,
                                           (acc[mf][j][1] + by) * esc);
            __half2 h1 = __floats2half2_rn((acc[mf][j][2] + bx) * esc,
                                           (acc[mf][j][3] + by) * esc);
            *(__half2*)&out[(long)row0 * DD + col] = h0;
            *(__half2*)&out[(long)(row0 + 8) * DD + col] = h1;
        }
    }
}

// ---------------------------------------------------------------------------
// Flash attention, max-free softmax (R13 structure) + diagonal-subtile
// fragment skipping: on the diagonal 64-key subtile, np/c chunks entirely
// above the causal boundary (P == 0 exactly) are skipped via a warp-uniform
// bound. Numerically identical to computing them.
// ---------------------------------------------------------------------------
#define QT 128
#define KTL 64
#define SDH 72
#define QBYTES (QT * SDH * 2)       // 18432
#define TILEB  (KTL * SDH * 2)      // 9216
#define STB    (2 * TILEB)          // 18432 (one 128-key stage)

__global__ __launch_bounds__(256, 2) void attn_tc(
    const __half* __restrict__ Q,
    const __half* __restrict__ K,
    const __half* __restrict__ V,
    float* __restrict__ out)
{
    extern __shared__ __align__(16) char smc[];
    const uint32_t sbase = (uint32_t)__cvta_generic_to_shared(smc);
    const uint32_t Qsa = sbase;
    const uint32_t Ksa = sbase + QBYTES;
    const uint32_t Vsa = Ksa + 2 * STB;

    const int tid  = threadIdx.x;
    const int lane = tid & 31;
    const int w    = tid >> 5;
    const int g    = lane >> 2;
    const int qd   = lane & 3;
    const int bh   = blockIdx.y;
    const int b    = bh / HH;
    const int h    = bh % HH;
    const int qi   = (int)gridDim.x - 1 - (int)blockIdx.x;
    const int q0   = qi * QT;
    const int wrow = w * 16;
    const long rowbase = (long)(b * SS) * DD + h * DH;
    const int nst = qi + 1;

    const int cr = tid >> 3;
    const int cc = (tid & 7) * 8;

#define SLOAD(st, stage)                                                     \
    {                                                                        \
        _Pragma("unroll")                                                    \
        for (int i = 0; i < 4; i++) {                                        \
            int r = i * 32 + cr;                                             \
            long ga = rowbase + (long)((st) * 128 + r) * DD + cc;            \
            CP16(Ksa + (stage) * STB + (r * SDH + cc) * 2, &K[ga]);          \
            CP16(Vsa + (stage) * STB + (r * SDH + cc) * 2, &V[ga]);          \
        }                                                                    \
        CP_COMMIT();                                                         \
    }

    // ---- prologue: Q + super-tile 0 ----
#pragma unroll
    for (int i = 0; i < 4; i++) {
        int r = i * 32 + cr;
        CP16(Qsa + (r * SDH + cc) * 2, &Q[rowbase + (long)(q0 + r) * DD + cc]);
    }
    SLOAD(0, 0);
    CP_WAIT0();
    __syncthreads();

    uint32_t qf[4][4];
    {
        uint32_t qa = Qsa + (((wrow + (lane & 15)) * SDH) + ((lane & 16) >> 1)) * 2;
#pragma unroll
        for (int k = 0; k < 4; k++)
            ldsm_x4(qf[k][0], qf[k][1], qf[k][2], qf[k][3], qa + k * 32);
    }

    float o[8][4];
#pragma unroll
    for (int n = 0; n < 8; n++)
#pragma unroll
        for (int j = 0; j < 4; j++) o[n][j] = 0.f;
    float oe[4] = {0.f, 0.f, 0.f, 0.f};

    const uint32_t ob = (g == 0) ? 0x3C003C00u : 0u;

    const int r0 = q0 + wrow + g;
    const int r1 = r0 + 8;
    const uint32_t ka0 = (((lane & 7) + ((lane & 16) >> 1)) * SDH + (lane & 8)) * 2;
    const uint32_t va0 = (((lane & 7) + (lane & 8)) * SDH + ((lane & 16) >> 1)) * 2;

#pragma unroll 1
    for (int st = 0; st < nst; st++) {
        if (st > 0) {
            CP_WAIT0();
            __syncthreads();
        }
        const int stage = st & 1;
        if (st + 1 < nst) SLOAD(st + 1, stage ^ 1);

#pragma unroll
        for (int j = 0; j < 2; j++) {
            const int kb = st * 128 + j * KTL;
            const int hi = q0 + wrow + 15;      // last unmasked key for this warp
            if (kb > hi) continue;              // fully masked subtile
            const bool dg = (kb + KTL - 1) > (q0 + wrow);
            // warp-uniform count of live 16-key chunks in this subtile (1..4)
            const int npq = dg ? ((hi - kb) >> 4) : 3;
            const uint32_t kbuf = Ksa + stage * STB + j * TILEB + ka0;
            const uint32_t vbuf = Vsa + stage * STB + j * TILEB + va0;

            // ---- S = Q @ K^T (log2-scaled scores, bounded) ----
            float s[8][4];
#pragma unroll
            for (int n = 0; n < 8; n++)
#pragma unroll
                for (int q = 0; q < 4; q++) s[n][q] = 0.f;

#pragma unroll
            for (int k = 0; k < 4; k++) {
#pragma unroll
                for (int np = 0; np < 4; np++) {
                    if (np > npq) continue;     // fully masked 16-key chunk
                    uint32_t b0, b1, b2, b3;
                    ldsm_x4(b0, b1, b2, b3, kbuf + (np * 16 * SDH + k * 16) * 2);
                    mma_f16(s[2 * np],     qf[k][0], qf[k][1], qf[k][2], qf[k][3], b0, b1);
                    mma_f16(s[2 * np + 1], qf[k][0], qf[k][1], qf[k][2], qf[k][3], b2, b3);
                }
            }

            // ---- causal mask (diagonal tiles only) ----
            if (dg) {
#pragma unroll
                for (int n = 0; n < 8; n++) {
                    if ((n >> 1) > npq) continue;
                    int c = kb + n * 8 + 2 * qd;
                    if (c     > r0) s[n][0] = MASKV;
                    if (c + 1 > r0) s[n][1] = MASKV;
                    if (c     > r1) s[n][2] = MASKV;
                    if (c + 1 > r1) s[n][3] = MASKV;
                }
            }

            // ---- P = exp2(s) in fp16, straight into PV mma ----
#pragma unroll
            for (int c = 0; c < 4; c++) {
                if (c > npq) continue;          // P == 0 exactly: skip
                uint32_t a0 = h2exp2(pack_h2(s[2 * c][0],     s[2 * c][1]));
                uint32_t a1 = h2exp2(pack_h2(s[2 * c][2],     s[2 * c][3]));
                uint32_t a2 = h2exp2(pack_h2(s[2 * c + 1][0], s[2 * c + 1][1]));
                uint32_t a3 = h2exp2(pack_h2(s[2 * c + 1][2], s[2 * c + 1][3]));
                mma_f16(oe, a0, a1, a2, a3, ob, ob);
#pragma unroll
                for (int np = 0; np < 4; np++) {
                    uint32_t b0, b1, b2, b3;
                    ldsm_x4_t(b0, b1, b2, b3, vbuf + (c * 16 * SDH + np * 16) * 2);
                    mma_f16(o[2 * np],     a0, a1, a2, a3, b0, b1);
                    mma_f16(o[2 * np + 1], a0, a1, a2, a3, b2, b3);
                }
            }
        }
    }

    // ---- epilogue: fetch row sums from qd==0 lanes, normalize, store ----
    float l0 = __shfl_sync(0xffffffffu, oe[0], lane & 28);
    float l1 = __shfl_sync(0xffffffffu, oe[2], lane & 28);
    float i0 = 1.f / l0, i1 = 1.f / l1;
#pragma unroll
    for (int n = 0; n < 8; n++) {
        float2 v0 = make_float2(o[n][0] * i0, o[n][1] * i0);
        float2 v1 = make_float2(o[n][2] * i1, o[n][3] * i1);
        *(float2*)&out[rowbase + (long)r0 * DD + n * 8 + 2 * qd] = v0;
        *(float2*)&out[rowbase + (long)r1 * DD + n * 8 + 2 * qd] = v1;
    }
}

// ---------------------------------------------------------------------------
extern "C" void kernel_launch(void* const* d_in, const int* in_sizes, int n_in,
                              void* d_out, int out_size)
{
    const float* X  = (const float*)d_in[0];
    const float* Wq = (const float*)d_in[2];
    const float* bq = (const float*)d_in[3];
    const float* Wk = (const float*)d_in[4];
    const float* bk = (const float*)d_in[5];
    const float* Wv = (const float*)d_in[6];
    const float* bv = (const float*)d_in[7];
    float* out = (float*)d_out;

    void *pxh, *pwh, *pq, *pk, *pv;
    cudaGetSymbolAddress(&pxh, g_xh);
    cudaGetSymbolAddress(&pwh, g_wh);
    cudaGetSymbolAddress(&pq, g_q);
    cudaGetSymbolAddress(&pk, g_k);
    cudaGetSymbolAddress(&pv, g_v);
    __half* xh = (__half*)pxh;
    __half* wh = (__half*)pwh;

    // packed conversion, 8 elems/thread (R13 configuration)
    cvt_pack<<<XB + 3 * WB, 256>>>(X, Wq, Wk, Wv, xh, wh);

    const int gsmem = NSTG * (ATB + BTB);   // 107520 B
    cudaFuncSetAttribute(gemm_h, cudaFuncAttributeMaxDynamicSharedMemorySize, gsmem);
    gemm_h<<<dim3(3 * (DD / 128), MM / 128), 256, gsmem>>>(
        xh, wh, bq, bk, bv, (__half*)pq, (__half*)pk, (__half*)pv);

    const int asmem = QBYTES + 4 * STB;   // 92160 B
    cudaFuncSetAttribute(attn_tc, cudaFuncAttributeMaxDynamicSharedMemorySize, asmem);
    attn_tc<<<dim3(SS / QT, BB * HH), 256, asmem>>>(
        (const __half*)pq, (const __half*)pk, (const __half*)pv, out);
}

// round 16
// speedup vs baseline: 1.0294x; 1.0294x over previous
#include <cuda_runtime.h>
#include <cuda_fp16.h>
#include <cstdint>

// Problem constants
#define BB 4
#define SS 2048
#define DD 768
#define HH 12
#define DH 64
#define MM (BB * SS)   // 8192 rows

// Scratch: fp16 copies of inputs + projections
__device__ __half g_xh[MM * DD];
__device__ __half g_wh[3 * DD * DD];
__device__ __half g_q[MM * DD];
__device__ __half g_k[MM * DD];
__device__ __half g_v[MM * DD];

__device__ __forceinline__ void mma_f16(float* c,
    uint32_t a0, uint32_t a1, uint32_t a2, uint32_t a3,
    uint32_t b0, uint32_t b1)
{
    asm volatile(
        "mma.sync.aligned.m16n8k16.row.col.f32.f16.f16.f32 "
        "{%0,%1,%2,%3},{%4,%5,%6,%7},{%8,%9},{%0,%1,%2,%3};"
        : "+f"(c[0]), "+f"(c[1]), "+f"(c[2]), "+f"(c[3])
        : "r"(a0), "r"(a1), "r"(a2), "r"(a3), "r"(b0), "r"(b1));
}

__device__ __forceinline__ void ldsm_x4(uint32_t& r0, uint32_t& r1,
    uint32_t& r2, uint32_t& r3, uint32_t addr)
{
    asm volatile("ldmatrix.sync.aligned.m8n8.x4.shared.b16 {%0,%1,%2,%3}, [%4];"
        : "=r"(r0), "=r"(r1), "=r"(r2), "=r"(r3) : "r"(addr));
}

__device__ __forceinline__ void ldsm_x4_t(uint32_t& r0, uint32_t& r1,
    uint32_t& r2, uint32_t& r3, uint32_t addr)
{
    asm volatile("ldmatrix.sync.aligned.m8n8.x4.trans.shared.b16 {%0,%1,%2,%3}, [%4];"
        : "=r"(r0), "=r"(r1), "=r"(r2), "=r"(r3) : "r"(addr));
}

__device__ __forceinline__ uint32_t pack_h2(float a, float b) {
    __half2 h = __floats2half2_rn(a, b);
    return *(uint32_t*)&h;
}

__device__ __forceinline__ uint32_t h2exp2(uint32_t x) {
    uint32_t r;
    asm("ex2.approx.f16x2 %0, %1;" : "=r"(r) : "r"(x));
    return r;
}

#define CP16(dst, src) \
    asm volatile("cp.async.cg.shared.global [%0], [%1], 16;" :: "r"(dst), "l"(src))
#define CP_COMMIT() asm volatile("cp.async.commit_group;")
#define CP_WAIT1()  asm volatile("cp.async.wait_group 1;")
#define CP_WAIT0()  asm volatile("cp.async.wait_group 0;")

#define SCL 0.18033688f   // 0.125 * log2(e), folded into Q projection
#define MASKV (-64.0f)    // exp2(-64) == 0 in fp16

// ---------------------------------------------------------------------------
// fp32 -> fp16 conversion: packed 1-D grid, 8 elems/thread (R13 shape).
// ---------------------------------------------------------------------------
#define XB (MM * DD / 8 / 256)     // 3072 blocks
#define WB (DD * DD / 8 / 256)     // 288 blocks

__global__ __launch_bounds__(256) void cvt_pack(
    const float* __restrict__ X,
    const float* __restrict__ wq, const float* __restrict__ wk,
    const float* __restrict__ wv,
    __half* __restrict__ xh, __half* __restrict__ wh)
{
    int bid = blockIdx.x;
    const float* src;
    __half* dst;
    if (bid < XB) {
        src = X; dst = xh;
    } else {
        bid -= XB;
        const int z = bid / WB;
        bid -= z * WB;
        src = (z == 0) ? wq : (z == 1) ? wk : wv;
        dst = wh + (long)z * DD * DD;
    }
    const long i = ((long)bid * 256 + threadIdx.x) * 8;
    float4 a = *(const float4*)&src[i];
    float4 b = *(const float4*)&src[i + 4];
    uint4 o;
    o.x = pack_h2(a.x, a.y);
    o.y = pack_h2(a.z, a.w);
    o.z = pack_h2(b.x, b.y);
    o.w = pack_h2(b.z, b.w);
    *(uint4*)&dst[i] = o;
}

// ---------------------------------------------------------------------------
// fp16 projection GEMM: BK=64, 3-stage cp.async, flat grid (frozen R13).
// z==0 (Q) output is pre-scaled by 0.125*log2(e).
// ---------------------------------------------------------------------------
#define HAS 72
#define HBS 136
#define ATB (128 * HAS * 2)   // 18432 B
#define BTB (64 * HBS * 2)    // 17408 B
#define NSTG 3

__global__ __launch_bounds__(256, 2) void gemm_h(
    const __half* __restrict__ Xh, const __half* __restrict__ Wh,
    const float* __restrict__ bq, const float* __restrict__ bk,
    const float* __restrict__ bv,
    __half* __restrict__ oq, __half* __restrict__ okk, __half* __restrict__ ov)
{
    const int z  = blockIdx.x / (DD / 128);
    const int nt = blockIdx.x % (DD / 128);
    const __half* W   = Wh + (long)z * DD * DD;
    const float* bias = (z == 0) ? bq : (z == 1) ? bk : bv;
    __half* out       = (z == 0) ? oq : (z == 1) ? okk : ov;
    const float esc   = (z == 0) ? SCL : 1.0f;

    extern __shared__ __align__(16) char smc[];
    const uint32_t sb  = (uint32_t)__cvta_generic_to_shared(smc);
    const uint32_t Asa = sb;
    const uint32_t Bsa = sb + NSTG * ATB;

    const int tid  = threadIdx.x;
    const int lane = tid & 31;
    const int w    = tid >> 5;
    const int g    = lane >> 2;
    const int qd   = lane & 3;
    const int wm   = w >> 2;
    const int wn   = w & 3;
    const int m0   = blockIdx.y * 128;
    const int n0   = nt * 128;

    float acc[4][4][4];
#pragma unroll
    for (int mf = 0; mf < 4; mf++)
#pragma unroll
        for (int j = 0; j < 4; j++)
#pragma unroll
            for (int q = 0; q < 4; q++) acc[mf][j][q] = 0.f;

#define LOADT(t, bsel)                                                        \
    {                                                                         \
        const int k0 = (t) * 64;                                              \
        _Pragma("unroll")                                                     \
        for (int i = 0; i < 4; i++) {                                         \
            int ch = i * 256 + tid;                                           \
            int r = ch >> 3, c = (ch & 7) * 8;                                \
            CP16(Asa + (bsel) * ATB + (r * HAS + c) * 2,                      \
                 &Xh[(long)(m0 + r) * DD + k0 + c]);                          \
        }                                                                     \
        _Pragma("unroll")                                                     \
        for (int i = 0; i < 4; i++) {                                         \
            int ch = i * 256 + tid;                                           \
            int r = ch >> 4, c = (ch & 15) * 8;                               \
            CP16(Bsa + (bsel) * BTB + (r * HBS + c) * 2,                      \
                 &W[(long)(k0 + r) * DD + n0 + c]);                           \
        }                                                                     \
        CP_COMMIT();                                                          \
    }

    LOADT(0, 0);
    LOADT(1, 1);

    const uint32_t aB = ((lane & 15) * HAS + ((lane & 16) >> 1)) * 2;
    const uint32_t bB = (((lane & 7) + (lane & 8)) * HBS + ((lane & 16) >> 1)) * 2;

    const int T = DD / 64;   // 12
#pragma unroll 1
    for (int t = 0; t < T; t++) {
        CP_WAIT1();
        __syncthreads();
        const int buf = t % NSTG;
        const uint32_t Ab = Asa + buf * ATB + aB + (wm * 64 * HAS) * 2;
        const uint32_t Bb = Bsa + buf * BTB + bB + (wn * 32) * 2;

        if (t + 2 < T) {
            LOADT(t + 2, (t + 2) % NSTG);
        } else {
            CP_COMMIT();
        }

#pragma unroll
        for (int ks = 0; ks < 4; ks++) {
            uint32_t a[4][4];
#pragma unroll
            for (int mf = 0; mf < 4; mf++)
                ldsm_x4(a[mf][0], a[mf][1], a[mf][2], a[mf][3],
                        Ab + (mf * 16 * HAS + ks * 16) * 2);
#pragma unroll
            for (int nf = 0; nf < 2; nf++) {
                uint32_t b0, b1, b2, b3;
                ldsm_x4_t(b0, b1, b2, b3, Bb + (ks * 16 * HBS + nf * 16) * 2);
#pragma unroll
                for (int mf = 0; mf < 4; mf++) {
                    mma_f16(acc[mf][2 * nf],     a[mf][0], a[mf][1], a[mf][2], a[mf][3], b0, b1);
                    mma_f16(acc[mf][2 * nf + 1], a[mf][0], a[mf][1], a[mf][2], a[mf][3], b2, b3);
                }
            }
        }
    }

#pragma unroll
    for (int mf = 0; mf < 4; mf++) {
        const int row0 = m0 + wm * 64 + mf * 16 + g;
#pragma unroll
        for (int j = 0; j < 4; j++) {
            const int col = n0 + wn * 32 + j * 8 + 2 * qd;
            const float bx = __ldg(&bias[col]);
            const float by = __ldg(&bias[col + 1]);
            __half2 h0 = __floats2half2_rn((acc[mf][j][0] + bx) * esc,
                                           (acc[mf][j][1] + by) * esc);
            __half2 h1 = __floats2half2_rn((acc[mf][j][2] + bx) * esc,
                                           (acc[mf][j][3] + by) * esc);
            *(__half2*)&out[(long)row0 * DD + col] = h0;
            *(__half2*)&out[(long)(row0 + 8) * DD + col] = h1;
        }
    }
}

// ---------------------------------------------------------------------------
// Flash attention, max-free softmax (exact R13 compute path).
// Pipeline reorder: prefetch issued BEFORE the cp.async wait
// (sync -> SLOAD(st+1) -> wait_group 1), matching gemm_h's proven shape.
// ---------------------------------------------------------------------------
#define QT 128
#define KTL 64
#define SDH 72
#define QBYTES (QT * SDH * 2)       // 18432
#define TILEB  (KTL * SDH * 2)      // 9216
#define STB    (2 * TILEB)          // 18432 (one 128-key stage)

__global__ __launch_bounds__(256, 2) void attn_tc(
    const __half* __restrict__ Q,
    const __half* __restrict__ K,
    const __half* __restrict__ V,
    float* __restrict__ out)
{
    extern __shared__ __align__(16) char smc[];
    const uint32_t sbase = (uint32_t)__cvta_generic_to_shared(smc);
    const uint32_t Qsa = sbase;
    const uint32_t Ksa = sbase + QBYTES;
    const uint32_t Vsa = Ksa + 2 * STB;

    const int tid  = threadIdx.x;
    const int lane = tid & 31;
    const int w    = tid >> 5;
    const int g    = lane >> 2;
    const int qd   = lane & 3;
    const int bh   = blockIdx.y;
    const int b    = bh / HH;
    const int h    = bh % HH;
    const int qi   = (int)gridDim.x - 1 - (int)blockIdx.x;
    const int q0   = qi * QT;
    const int wrow = w * 16;
    const long rowbase = (long)(b * SS) * DD + h * DH;
    const int nst = qi + 1;

    const int cr = tid >> 3;
    const int cc = (tid & 7) * 8;

#define SLOAD(st, stage)                                                     \
    {                                                                        \
        _Pragma("unroll")                                                    \
        for (int i = 0; i < 4; i++) {                                        \
            int r = i * 32 + cr;                                             \
            long ga = rowbase + (long)((st) * 128 + r) * DD + cc;            \
            CP16(Ksa + (stage) * STB + (r * SDH + cc) * 2, &K[ga]);          \
            CP16(Vsa + (stage) * STB + (r * SDH + cc) * 2, &V[ga]);          \
        }                                                                    \
        CP_COMMIT();                                                         \
    }

    // ---- prologue: Q + super-tile 0 (one group) ----
#pragma unroll
    for (int i = 0; i < 4; i++) {
        int r = i * 32 + cr;
        CP16(Qsa + (r * SDH + cc) * 2, &Q[rowbase + (long)(q0 + r) * DD + cc]);
    }
    SLOAD(0, 0);
    CP_WAIT0();
    __syncthreads();

    uint32_t qf[4][4];
    {
        uint32_t qa = Qsa + (((wrow + (lane & 15)) * SDH) + ((lane & 16) >> 1)) * 2;
#pragma unroll
        for (int k = 0; k < 4; k++)
            ldsm_x4(qf[k][0], qf[k][1], qf[k][2], qf[k][3], qa + k * 32);
    }

    float o[8][4];
#pragma unroll
    for (int n = 0; n < 8; n++)
#pragma unroll
        for (int j = 0; j < 4; j++) o[n][j] = 0.f;
    float oe[4] = {0.f, 0.f, 0.f, 0.f};

    const uint32_t ob = (g == 0) ? 0x3C003C00u : 0u;

    const int r0 = q0 + wrow + g;
    const int r1 = r0 + 8;
    const uint32_t ka0 = (((lane & 7) + ((lane & 16) >> 1)) * SDH + (lane & 8)) * 2;
    const uint32_t va0 = (((lane & 7) + (lane & 8)) * SDH + ((lane & 16) >> 1)) * 2;

#pragma unroll 1
    for (int st = 0; st < nst; st++) {
        const int stage = st & 1;
        // sync: all warps done consuming stage^1 (super-tile st-1)
        if (st > 0) __syncthreads();
        // issue prefetch for st+1 BEFORE waiting on st (kept in flight)
        if (st + 1 < nst) {
            SLOAD(st + 1, stage ^ 1);
        } else {
            CP_COMMIT();   // empty group keeps wait_group count aligned
        }
        // wait for SLOAD(st) (the older of the two outstanding groups)
        if (st > 0) CP_WAIT1();

#pragma unroll
        for (int j = 0; j < 2; j++) {
            const int kb = st * 128 + j * KTL;
            if (kb > q0 + wrow + 15) continue;   // fully masked for this warp
            const uint32_t kbuf = Ksa + stage * STB + j * TILEB + ka0;
            const uint32_t vbuf = Vsa + stage * STB + j * TILEB + va0;

            // ---- S = Q @ K^T (log2-scaled scores, bounded) ----
            float s[8][4];
#pragma unroll
            for (int n = 0; n < 8; n++)
#pragma unroll
                for (int q = 0; q < 4; q++) s[n][q] = 0.f;

#pragma unroll
            for (int k = 0; k < 4; k++) {
#pragma unroll
                for (int np = 0; np < 4; np++) {
                    uint32_t b0, b1, b2, b3;
                    ldsm_x4(b0, b1, b2, b3, kbuf + (np * 16 * SDH + k * 16) * 2);
                    mma_f16(s[2 * np],     qf[k][0], qf[k][1], qf[k][2], qf[k][3], b0, b1);
                    mma_f16(s[2 * np + 1], qf[k][0], qf[k][1], qf[k][2], qf[k][3], b2, b3);
                }
            }

            // ---- causal mask (diagonal tiles only) ----
            const bool dg = (kb + KTL - 1) > (q0 + wrow);
            if (dg) {
#pragma unroll
                for (int n = 0; n < 8; n++) {
                    int c = kb + n * 8 + 2 * qd;
                    if (c     > r0) s[n][0] = MASKV;
                    if (c + 1 > r0) s[n][1] = MASKV;
                    if (c     > r1) s[n][2] = MASKV;
                    if (c + 1 > r1) s[n][3] = MASKV;
                }
            }

            // ---- P = exp2(s) in fp16, straight into PV mma ----
#pragma unroll
            for (int c = 0; c < 4; c++) {
                uint32_t a0 = h2exp2(pack_h2(s[2 * c][0],     s[2 * c][1]));
                uint32_t a1 = h2exp2(pack_h2(s[2 * c][2],     s[2 * c][3]));
                uint32_t a2 = h2exp2(pack_h2(s[2 * c + 1][0], s[2 * c + 1][1]));
                uint32_t a3 = h2exp2(pack_h2(s[2 * c + 1][2], s[2 * c + 1][3]));
                mma_f16(oe, a0, a1, a2, a3, ob, ob);
#pragma unroll
                for (int np = 0; np < 4; np++) {
                    uint32_t b0, b1, b2, b3;
                    ldsm_x4_t(b0, b1, b2, b3, vbuf + (c * 16 * SDH + np * 16) * 2);
                    mma_f16(o[2 * np],     a0, a1, a2, a3, b0, b1);
                    mma_f16(o[2 * np + 1], a0, a1, a2, a3, b2, b3);
                }
            }
        }
    }

    // ---- epilogue: fetch row sums from qd==0 lanes, normalize, store ----
    float l0 = __shfl_sync(0xffffffffu, oe[0], lane & 28);
    float l1 = __shfl_sync(0xffffffffu, oe[2], lane & 28);
    float i0 = 1.f / l0, i1 = 1.f / l1;
#pragma unroll
    for (int n = 0; n < 8; n++) {
        float2 v0 = make_float2(o[n][0] * i0, o[n][1] * i0);
        float2 v1 = make_float2(o[n][2] * i1, o[n][3] * i1);
        *(float2*)&out[rowbase + (long)r0 * DD + n * 8 + 2 * qd] = v0;
        *(float2*)&out[rowbase + (long)r1 * DD + n * 8 + 2 * qd] = v1;
    }
}

// ---------------------------------------------------------------------------
extern "C" void kernel_launch(void* const* d_in, const int* in_sizes, int n_in,
                              void* d_out, int out_size)
{
    const float* X  = (const float*)d_in[0];
    const float* Wq = (const float*)d_in[2];
    const float* bq = (const float*)d_in[3];
    const float* Wk = (const float*)d_in[4];
    const float* bk = (const float*)d_in[5];
    const float* Wv = (const float*)d_in[6];
    const float* bv = (const float*)d_in[7];
    float* out = (float*)d_out;

    void *pxh, *pwh, *pq, *pk, *pv;
    cudaGetSymbolAddress(&pxh, g_xh);
    cudaGetSymbolAddress(&pwh, g_wh);
    cudaGetSymbolAddress(&pq, g_q);
    cudaGetSymbolAddress(&pk, g_k);
    cudaGetSymbolAddress(&pv, g_v);
    __half* xh = (__half*)pxh;
    __half* wh = (__half*)pwh;

    // packed conversion, 8 elems/thread
    cvt_pack<<<XB + 3 * WB, 256>>>(X, Wq, Wk, Wv, xh, wh);

    const int gsmem = NSTG * (ATB + BTB);   // 107520 B
    cudaFuncSetAttribute(gemm_h, cudaFuncAttributeMaxDynamicSharedMemorySize, gsmem);
    gemm_h<<<dim3(3 * (DD / 128), MM / 128), 256, gsmem>>>(
        xh, wh, bq, bk, bv, (__half*)pq, (__half*)pk, (__half*)pv);

    const int asmem = QBYTES + 4 * STB;   // 92160 B
    cudaFuncSetAttribute(attn_tc, cudaFuncAttributeMaxDynamicSharedMemorySize, asmem);
    attn_tc<<<dim3(SS / QT, BB * HH), 256, asmem>>>(
        (const __half*)pq, (const __half*)pk, (const __half*)pv, out);
}

// round 17
// speedup vs baseline: 1.1614x; 1.1283x over previous
#include <cuda_runtime.h>
#include <cuda_fp16.h>
#include <cstdint>

// Problem constants
#define BB 4
#define SS 2048
#define DD 768
#define HH 12
#define DH 64
#define MM (BB * SS)   // 8192 rows

// Scratch: fp16 copies of inputs + projections
__device__ __half g_xh[MM * DD];
__device__ __half g_wh[3 * DD * DD];
__device__ __half g_q[MM * DD];
__device__ __half g_k[MM * DD];
__device__ __half g_v[MM * DD];

__device__ __forceinline__ void mma_f16(float* c,
    uint32_t a0, uint32_t a1, uint32_t a2, uint32_t a3,
    uint32_t b0, uint32_t b1)
{
    asm volatile(
        "mma.sync.aligned.m16n8k16.row.col.f32.f16.f16.f32 "
        "{%0,%1,%2,%3},{%4,%5,%6,%7},{%8,%9},{%0,%1,%2,%3};"
        : "+f"(c[0]), "+f"(c[1]), "+f"(c[2]), "+f"(c[3])
        : "r"(a0), "r"(a1), "r"(a2), "r"(a3), "r"(b0), "r"(b1));
}

__device__ __forceinline__ void ldsm_x4(uint32_t& r0, uint32_t& r1,
    uint32_t& r2, uint32_t& r3, uint32_t addr)
{
    asm volatile("ldmatrix.sync.aligned.m8n8.x4.shared.b16 {%0,%1,%2,%3}, [%4];"
        : "=r"(r0), "=r"(r1), "=r"(r2), "=r"(r3) : "r"(addr));
}

__device__ __forceinline__ void ldsm_x4_t(uint32_t& r0, uint32_t& r1,
    uint32_t& r2, uint32_t& r3, uint32_t addr)
{
    asm volatile("ldmatrix.sync.aligned.m8n8.x4.trans.shared.b16 {%0,%1,%2,%3}, [%4];"
        : "=r"(r0), "=r"(r1), "=r"(r2), "=r"(r3) : "r"(addr));
}

__device__ __forceinline__ uint32_t pack_h2(float a, float b) {
    __half2 h = __floats2half2_rn(a, b);
    return *(uint32_t*)&h;
}

__device__ __forceinline__ uint32_t h2exp2(uint32_t x) {
    uint32_t r;
    asm("ex2.approx.f16x2 %0, %1;" : "=r"(r) : "r"(x));
    return r;
}

#define CP16(dst, src) \
    asm volatile("cp.async.cg.shared.global [%0], [%1], 16;" :: "r"(dst), "l"(src))
#define CP_COMMIT() asm volatile("cp.async.commit_group;")
#define CP_WAIT1()  asm volatile("cp.async.wait_group 1;")
#define CP_WAIT0()  asm volatile("cp.async.wait_group 0;")

#define SCL 0.18033688f   // 0.125 * log2(e), folded into Q projection
#define MASKV (-64.0f)    // exp2(-64) == 0 in fp16

// ---------------------------------------------------------------------------
// fp32 -> fp16 conversion: packed 1-D grid, 8 elems/thread.
// ---------------------------------------------------------------------------
#define XB (MM * DD / 8 / 256)     // 3072 blocks
#define WB (DD * DD / 8 / 256)     // 288 blocks

__global__ __launch_bounds__(256) void cvt_pack(
    const float* __restrict__ X,
    const float* __restrict__ wq, const float* __restrict__ wk,
    const float* __restrict__ wv,
    __half* __restrict__ xh, __half* __restrict__ wh)
{
    int bid = blockIdx.x;
    const float* src;
    __half* dst;
    if (bid < XB) {
        src = X; dst = xh;
    } else {
        bid -= XB;
        const int z = bid / WB;
        bid -= z * WB;
        src = (z == 0) ? wq : (z == 1) ? wk : wv;
        dst = wh + (long)z * DD * DD;
    }
    const long i = ((long)bid * 256 + threadIdx.x) * 8;
    float4 a = *(const float4*)&src[i];
    float4 b = *(const float4*)&src[i + 4];
    uint4 o;
    o.x = pack_h2(a.x, a.y);
    o.y = pack_h2(a.z, a.w);
    o.z = pack_h2(b.x, b.y);
    o.w = pack_h2(b.z, b.w);
    *(uint4*)&dst[i] = o;
}

// ---------------------------------------------------------------------------
// fp16 projection GEMM: BK=64, 3-stage cp.async, flat grid (frozen).
// z==0 (Q) output is pre-scaled by 0.125*log2(e).
// ---------------------------------------------------------------------------
#define HAS 72
#define HBS 136
#define ATB (128 * HAS * 2)   // 18432 B
#define BTB (64 * HBS * 2)    // 17408 B
#define NSTG 3

__global__ __launch_bounds__(256, 2) void gemm_h(
    const __half* __restrict__ Xh, const __half* __restrict__ Wh,
    const float* __restrict__ bq, const float* __restrict__ bk,
    const float* __restrict__ bv,
    __half* __restrict__ oq, __half* __restrict__ okk, __half* __restrict__ ov)
{
    const int z  = blockIdx.x / (DD / 128);
    const int nt = blockIdx.x % (DD / 128);
    const __half* W   = Wh + (long)z * DD * DD;
    const float* bias = (z == 0) ? bq : (z == 1) ? bk : bv;
    __half* out       = (z == 0) ? oq : (z == 1) ? okk : ov;
    const float esc   = (z == 0) ? SCL : 1.0f;

    extern __shared__ __align__(16) char smc[];
    const uint32_t sb  = (uint32_t)__cvta_generic_to_shared(smc);
    const uint32_t Asa = sb;
    const uint32_t Bsa = sb + NSTG * ATB;

    const int tid  = threadIdx.x;
    const int lane = tid & 31;
    const int w    = tid >> 5;
    const int g    = lane >> 2;
    const int qd   = lane & 3;
    const int wm   = w >> 2;
    const int wn   = w & 3;
    const int m0   = blockIdx.y * 128;
    const int n0   = nt * 128;

    float acc[4][4][4];
#pragma unroll
    for (int mf = 0; mf < 4; mf++)
#pragma unroll
        for (int j = 0; j < 4; j++)
#pragma unroll
            for (int q = 0; q < 4; q++) acc[mf][j][q] = 0.f;

#define LOADT(t, bsel)                                                        \
    {                                                                         \
        const int k0 = (t) * 64;                                              \
        _Pragma("unroll")                                                     \
        for (int i = 0; i < 4; i++) {                                         \
            int ch = i * 256 + tid;                                           \
            int r = ch >> 3, c = (ch & 7) * 8;                                \
            CP16(Asa + (bsel) * ATB + (r * HAS + c) * 2,                      \
                 &Xh[(long)(m0 + r) * DD + k0 + c]);                          \
        }                                                                     \
        _Pragma("unroll")                                                     \
        for (int i = 0; i < 4; i++) {                                         \
            int ch = i * 256 + tid;                                           \
            int r = ch >> 4, c = (ch & 15) * 8;                               \
            CP16(Bsa + (bsel) * BTB + (r * HBS + c) * 2,                      \
                 &W[(long)(k0 + r) * DD + n0 + c]);                           \
        }                                                                     \
        CP_COMMIT();                                                          \
    }

    LOADT(0, 0);
    LOADT(1, 1);

    const uint32_t aB = ((lane & 15) * HAS + ((lane & 16) >> 1)) * 2;
    const uint32_t bB = (((lane & 7) + (lane & 8)) * HBS + ((lane & 16) >> 1)) * 2;

    const int T = DD / 64;   // 12
#pragma unroll 1
    for (int t = 0; t < T; t++) {
        CP_WAIT1();
        __syncthreads();
        const int buf = t % NSTG;
        const uint32_t Ab = Asa + buf * ATB + aB + (wm * 64 * HAS) * 2;
        const uint32_t Bb = Bsa + buf * BTB + bB + (wn * 32) * 2;

        if (t + 2 < T) {
            LOADT(t + 2, (t + 2) % NSTG);
        } else {
            CP_COMMIT();
        }

#pragma unroll
        for (int ks = 0; ks < 4; ks++) {
            uint32_t a[4][4];
#pragma unroll
            for (int mf = 0; mf < 4; mf++)
                ldsm_x4(a[mf][0], a[mf][1], a[mf][2], a[mf][3],
                        Ab + (mf * 16 * HAS + ks * 16) * 2);
#pragma unroll
            for (int nf = 0; nf < 2; nf++) {
                uint32_t b0, b1, b2, b3;
                ldsm_x4_t(b0, b1, b2, b3, Bb + (ks * 16 * HBS + nf * 16) * 2);
#pragma unroll
                for (int mf = 0; mf < 4; mf++) {
                    mma_f16(acc[mf][2 * nf],     a[mf][0], a[mf][1], a[mf][2], a[mf][3], b0, b1);
                    mma_f16(acc[mf][2 * nf + 1], a[mf][0], a[mf][1], a[mf][2], a[mf][3], b2, b3);
                }
            }
        }
    }

#pragma unroll
    for (int mf = 0; mf < 4; mf++) {
        const int row0 = m0 + wm * 64 + mf * 16 + g;
#pragma unroll
        for (int j = 0; j < 4; j++) {
            const int col = n0 + wn * 32 + j * 8 + 2 * qd;
            const float bx = __ldg(&bias[col]);
            const float by = __ldg(&bias[col + 1]);
            __half2 h0 = __floats2half2_rn((acc[mf][j][0] + bx) * esc,
                                           (acc[mf][j][1] + by) * esc);
            __half2 h1 = __floats2half2_rn((acc[mf][j][2] + bx) * esc,
                                           (acc[mf][j][3] + by) * esc);
            *(__half2*)&out[(long)row0 * DD + col] = h0;
            *(__half2*)&out[(long)(row0 + 8) * DD + col] = h1;
        }
    }
}

// ---------------------------------------------------------------------------
// Flash attention, max-free softmax (R16 compute path, unchanged).
// GRID REORDER: blockIdx.x = (b,h), blockIdx.y = query tile (reversed) —
// all 48 heaviest CTAs (qi=15) get the lowest bids and launch FIRST,
// eliminating the ~25% straggler tail of the old (qtile, bh) layout.
// ---------------------------------------------------------------------------
#define QT 128
#define KTL 64
#define SDH 72
#define QBYTES (QT * SDH * 2)       // 18432
#define TILEB  (KTL * SDH * 2)      // 9216
#define STB    (2 * TILEB)          // 18432 (one 128-key stage)

__global__ __launch_bounds__(256, 2) void attn_tc(
    const __half* __restrict__ Q,
    const __half* __restrict__ K,
    const __half* __restrict__ V,
    float* __restrict__ out)
{
    extern __shared__ __align__(16) char smc[];
    const uint32_t sbase = (uint32_t)__cvta_generic_to_shared(smc);
    const uint32_t Qsa = sbase;
    const uint32_t Ksa = sbase + QBYTES;
    const uint32_t Vsa = Ksa + 2 * STB;

    const int tid  = threadIdx.x;
    const int lane = tid & 31;
    const int w    = tid >> 5;
    const int g    = lane >> 2;
    const int qd   = lane & 3;
    const int bh   = blockIdx.x;                              // (b,h) = fast axis
    const int b    = bh / HH;
    const int h    = bh % HH;
    const int qi   = (int)gridDim.y - 1 - (int)blockIdx.y;    // heavy tiles first
    const int q0   = qi * QT;
    const int wrow = w * 16;
    const long rowbase = (long)(b * SS) * DD + h * DH;
    const int nst = qi + 1;

    const int cr = tid >> 3;
    const int cc = (tid & 7) * 8;

#define SLOAD(st, stage)                                                     \
    {                                                                        \
        _Pragma("unroll")                                                    \
        for (int i = 0; i < 4; i++) {                                        \
            int r = i * 32 + cr;                                             \
            long ga = rowbase + (long)((st) * 128 + r) * DD + cc;            \
            CP16(Ksa + (stage) * STB + (r * SDH + cc) * 2, &K[ga]);          \
            CP16(Vsa + (stage) * STB + (r * SDH + cc) * 2, &V[ga]);          \
        }                                                                    \
        CP_COMMIT();                                                         \
    }

    // ---- prologue: Q + super-tile 0 (one group) ----
#pragma unroll
    for (int i = 0; i < 4; i++) {
        int r = i * 32 + cr;
        CP16(Qsa + (r * SDH + cc) * 2, &Q[rowbase + (long)(q0 + r) * DD + cc]);
    }
    SLOAD(0, 0);
    CP_WAIT0();
    __syncthreads();

    uint32_t qf[4][4];
    {
        uint32_t qa = Qsa + (((wrow + (lane & 15)) * SDH) + ((lane & 16) >> 1)) * 2;
#pragma unroll
        for (int k = 0; k < 4; k++)
            ldsm_x4(qf[k][0], qf[k][1], qf[k][2], qf[k][3], qa + k * 32);
    }

    float o[8][4];
#pragma unroll
    for (int n = 0; n < 8; n++)
#pragma unroll
        for (int j = 0; j < 4; j++) o[n][j] = 0.f;
    float oe[4] = {0.f, 0.f, 0.f, 0.f};

    const uint32_t ob = (g == 0) ? 0x3C003C00u : 0u;

    const int r0 = q0 + wrow + g;
    const int r1 = r0 + 8;
    const uint32_t ka0 = (((lane & 7) + ((lane & 16) >> 1)) * SDH + (lane & 8)) * 2;
    const uint32_t va0 = (((lane & 7) + (lane & 8)) * SDH + ((lane & 16) >> 1)) * 2;

#pragma unroll 1
    for (int st = 0; st < nst; st++) {
        const int stage = st & 1;
        if (st > 0) __syncthreads();
        if (st + 1 < nst) {
            SLOAD(st + 1, stage ^ 1);
        } else {
            CP_COMMIT();
        }
        if (st > 0) CP_WAIT1();

#pragma unroll
        for (int j = 0; j < 2; j++) {
            const int kb = st * 128 + j * KTL;
            if (kb > q0 + wrow + 15) continue;   // fully masked for this warp
            const uint32_t kbuf = Ksa + stage * STB + j * TILEB + ka0;
            const uint32_t vbuf = Vsa + stage * STB + j * TILEB + va0;

            // ---- S = Q @ K^T (log2-scaled scores, bounded) ----
            float s[8][4];
#pragma unroll
            for (int n = 0; n < 8; n++)
#pragma unroll
                for (int q = 0; q < 4; q++) s[n][q] = 0.f;

#pragma unroll
            for (int k = 0; k < 4; k++) {
#pragma unroll
                for (int np = 0; np < 4; np++) {
                    uint32_t b0, b1, b2, b3;
                    ldsm_x4(b0, b1, b2, b3, kbuf + (np * 16 * SDH + k * 16) * 2);
                    mma_f16(s[2 * np],     qf[k][0], qf[k][1], qf[k][2], qf[k][3], b0, b1);
                    mma_f16(s[2 * np + 1], qf[k][0], qf[k][1], qf[k][2], qf[k][3], b2, b3);
                }
            }

            // ---- causal mask (diagonal tiles only) ----
            const bool dg = (kb + KTL - 1) > (q0 + wrow);
            if (dg) {
#pragma unroll
                for (int n = 0; n < 8; n++) {
                    int c = kb + n * 8 + 2 * qd;
                    if (c     > r0) s[n][0] = MASKV;
                    if (c + 1 > r0) s[n][1] = MASKV;
                    if (c     > r1) s[n][2] = MASKV;
                    if (c + 1 > r1) s[n][3] = MASKV;
                }
            }

            // ---- P = exp2(s) in fp16, straight into PV mma ----
#pragma unroll
            for (int c = 0; c < 4; c++) {
                uint32_t a0 = h2exp2(pack_h2(s[2 * c][0],     s[2 * c][1]));
                uint32_t a1 = h2exp2(pack_h2(s[2 * c][2],     s[2 * c][3]));
                uint32_t a2 = h2exp2(pack_h2(s[2 * c + 1][0], s[2 * c + 1][1]));
                uint32_t a3 = h2exp2(pack_h2(s[2 * c + 1][2], s[2 * c + 1][3]));
                mma_f16(oe, a0, a1, a2, a3, ob, ob);
#pragma unroll
                for (int np = 0; np < 4; np++) {
                    uint32_t b0, b1, b2, b3;
                    ldsm_x4_t(b0, b1, b2, b3, vbuf + (c * 16 * SDH + np * 16) * 2);
                    mma_f16(o[2 * np],     a0, a1, a2, a3, b0, b1);
                    mma_f16(o[2 * np + 1], a0, a1, a2, a3, b2, b3);
                }
            }
        }
    }

    // ---- epilogue: fetch row sums from qd==0 lanes, normalize, store ----
    float l0 = __shfl_sync(0xffffffffu, oe[0], lane & 28);
    float l1 = __shfl_sync(0xffffffffu, oe[2], lane & 28);
    float i0 = 1.f / l0, i1 = 1.f / l1;
#pragma unroll
    for (int n = 0; n < 8; n++) {
        float2 v0 = make_float2(o[n][0] * i0, o[n][1] * i0);
        float2 v1 = make_float2(o[n][2] * i1, o[n][3] * i1);
        *(float2*)&out[rowbase + (long)r0 * DD + n * 8 + 2 * qd] = v0;
        *(float2*)&out[rowbase + (long)r1 * DD + n * 8 + 2 * qd] = v1;
    }
}

// ---------------------------------------------------------------------------
extern "C" void kernel_launch(void* const* d_in, const int* in_sizes, int n_in,
                              void* d_out, int out_size)
{
    const float* X  = (const float*)d_in[0];
    const float* Wq = (const float*)d_in[2];
    const float* bq = (const float*)d_in[3];
    const float* Wk = (const float*)d_in[4];
    const float* bk = (const float*)d_in[5];
    const float* Wv = (const float*)d_in[6];
    const float* bv = (const float*)d_in[7];
    float* out = (float*)d_out;

    void *pxh, *pwh, *pq, *pk, *pv;
    cudaGetSymbolAddress(&pxh, g_xh);
    cudaGetSymbolAddress(&pwh, g_wh);
    cudaGetSymbolAddress(&pq, g_q);
    cudaGetSymbolAddress(&pk, g_k);
    cudaGetSymbolAddress(&pv, g_v);
    __half* xh = (__half*)pxh;
    __half* wh = (__half*)pwh;

    // packed conversion, 8 elems/thread
    cvt_pack<<<XB + 3 * WB, 256>>>(X, Wq, Wk, Wv, xh, wh);

    const int gsmem = NSTG * (ATB + BTB);   // 107520 B
    cudaFuncSetAttribute(gemm_h, cudaFuncAttributeMaxDynamicSharedMemorySize, gsmem);
    gemm_h<<<dim3(3 * (DD / 128), MM / 128), 256, gsmem>>>(
        xh, wh, bq, bk, bv, (__half*)pq, (__half*)pk, (__half*)pv);

    // attention: grid (bh, qtile) -> global heavy-first launch order
    const int asmem = QBYTES + 4 * STB;   // 92160 B
    cudaFuncSetAttribute(attn_tc, cudaFuncAttributeMaxDynamicSharedMemorySize, asmem);
    attn_tc<<<dim3(BB * HH, SS / QT), 256, asmem>>>(
        (const __half*)pq, (const __half*)pk, (const __half*)pv, out);
}